// round 12
// baseline (speedup 1.0000x reference)
#include <cuda_runtime.h>
#include <math.h>

// out[b,i,j] = pos_biases[j - i + n - 1]
//            + ts_w[ clamp( floor( log(clip(|f32(t[min(i+1,n-1)]) - f32(t[j])|, 1, 1e9)) / 0.301 ), 0, nb ) ]
//
// R6 exact core (measured best): biased-trunc __log2f + host-built ulp-exact
// threshold table, fused (thr[k], w[k-1], w[k]); one LDS.128 + compare per
// element. R11: 4 rows/block (halved live state -> fewer regs, higher occ),
// dense tid*4 column mapping, zero per-row predicates (i0 clamped).
// rel_err identical to R3-R10: 4.933e-4.

struct ThrTab { float thr[80]; };

__global__ void __launch_bounds__(256)
bias_kernel(const int*   __restrict__ ts,
            const float* __restrict__ pos,
            const float* __restrict__ tsw,
            float*       __restrict__ out,
            int n, int nb, ThrTab tab) {
    extern __shared__ float sm[];
    float4* s_tab = (float4*)sm;              // 80 x (thr[k], w[k-1], w[k], 0)
    float*  s_pos = sm + 320;                 // n + 8 floats

    const int b   = blockIdx.y;
    int i0 = blockIdx.x * 4;
    if (i0 > n - 4) i0 = (n > 4) ? (n - 4) : 0;   // clamp: dup rows write identical data
    const int tid = threadIdx.x;
    const int* trow = ts + (size_t)b * n;

    if (tid < 80) {
        int k = tid;
        float wkm1 = tsw[min(max(k - 1, 0), nb)];
        float wk   = tsw[min(k, nb)];
        s_tab[k] = make_float4(tab.thr[k], wkm1, wk, 0.0f);
    }
    const int pbase = n - 4 - i0;             // pos idx of s_pos[0]
    for (int idx = tid; idx < n + 8; idx += 256) {
        int g = pbase + idx;
        s_pos[idx] = (g >= 0 && g <= 2 * n - 2) ? pos[g] : 0.0f;
    }
    __syncthreads();

    float tnr[4];
    #pragma unroll
    for (int r = 0; r < 4; ++r) tnr[r] = (float)__ldg(&trow[min(i0 + r + 1, n - 1)]);

    float* oblk = out + ((size_t)b * n + i0) * (size_t)n;

    for (int jj = tid * 4; jj < n; jj += 1024) {
        int4 ti = *reinterpret_cast<const int4*>(trow + jj);
        const float tv0 = (float)ti.x, tv1 = (float)ti.y,
                    tv2 = (float)ti.z, tv3 = (float)ti.w;
        float4 p0 = *reinterpret_cast<const float4*>(s_pos + jj);
        float4 p1 = *reinterpret_cast<const float4*>(s_pos + jj + 4);
        const float pw[8] = {p0.x, p0.y, p0.z, p0.w,
                             p1.x, p1.y, p1.z, p1.w};
        float* op = oblk + jj;

        #pragma unroll
        for (int r = 0; r < 4; ++r) {
            const float tn = tnr[r];
            float w0, w1, w2, w3;
            {
                float x = fmaxf(fabsf(tn - tv0), 1.0f);
                float q = fmaf(__log2f(x), 2.3028145f, 1.25e-4f);
                float4 te = s_tab[(int)q];
                w0 = (x < te.x) ? te.y : te.z;
            }
            {
                float x = fmaxf(fabsf(tn - tv1), 1.0f);
                float q = fmaf(__log2f(x), 2.3028145f, 1.25e-4f);
                float4 te = s_tab[(int)q];
                w1 = (x < te.x) ? te.y : te.z;
            }
            {
                float x = fmaxf(fabsf(tn - tv2), 1.0f);
                float q = fmaf(__log2f(x), 2.3028145f, 1.25e-4f);
                float4 te = s_tab[(int)q];
                w2 = (x < te.x) ? te.y : te.z;
            }
            {
                float x = fmaxf(fabsf(tn - tv3), 1.0f);
                float q = fmaf(__log2f(x), 2.3028145f, 1.25e-4f);
                float4 te = s_tab[(int)q];
                w3 = (x < te.x) ? te.y : te.z;
            }
            float4 o;
            o.x = w0 + pw[3 - r];
            o.y = w1 + pw[4 - r];
            o.z = w2 + pw[5 - r];
            o.w = w3 + pw[6 - r];
            *reinterpret_cast<float4*>(op) = o;
            op += n;
        }
    }
}

static void build_thresholds_host(ThrTab* tab) {
    typedef union { float f; unsigned u; } FU;
    for (int k = 0; k < 80; ++k) {
        if (k == 0) { tab->thr[0] = 1.0f; continue; }
        volatile float kb = 0.301f;                  // force f32 division semantics
        FU l; l.f = (float)(0.301 * (double)k);
        while (!((float)(l.f / kb) >= (float)k)) l.u += 1u;
        for (;;) {
            FU p; p.u = l.u - 1u;
            if ((float)(p.f / kb) >= (float)k) l.u = p.u; else break;
        }
        FU x; x.f = (float)exp((double)l.f);
        while (!((float)log((double)x.f) >= l.f)) x.u += 1u;
        for (;;) {
            FU p; p.u = x.u - 1u;
            if ((float)log((double)p.f) >= l.f) x.u = p.u; else break;
        }
        tab->thr[k] = x.f;
    }
}

extern "C" void kernel_launch(void* const* d_in, const int* in_sizes, int n_in,
                              void* d_out, int out_size) {
    const int*   ts  = (const int*)d_in[0];     // timestamps (B*N) int32
    const float* pos = (const float*)d_in[1];   // pos_biases (2N-1) f32
    const float* tsw = (const float*)d_in[2];   // ts_w (nb+1) f32

    const int n  = (in_sizes[1] + 1) / 2;
    const int B  = in_sizes[0] / n;
    const int nb = in_sizes[2] - 1;

    ThrTab tab;
    build_thresholds_host(&tab);

    size_t smem = (size_t)(320 + n + 8) * sizeof(float);
    dim3 grid((n + 3) / 4, B);
    bias_kernel<<<grid, 256, smem>>>(ts, pos, tsw, (float*)d_out, n, nb, tab);
}

// round 13
// speedup vs baseline: 1.1287x; 1.1287x over previous
#include <cuda_runtime.h>
#include <math.h>

// out[b,i,j] = pos_biases[j - i + n - 1]
//            + ts_w[ clamp( floor( log(clip(|f32(t[min(i+1,n-1)]) - f32(t[j])|, 1, 1e9)) / 0.301 ), 0, nb ) ]
//
// R6 exact core (measured best): biased-trunc __log2f + host-built ulp-exact
// threshold table fused as (thr[k], w[k-1], w[k]); one LDS.128 + compare/select
// per element. R12: compile-time n=2048 specialization -> immediate-offset
// stores (no per-row IADD), no tail predicates, constant addressing; reg cap
// via launch_bounds(256,6). Generic fallback for other shapes.
// rel_err identical to R3-R11: 4.933e-4.

struct ThrTab { float thr[80]; };

// ---------------- specialized kernel: n == 2048 ----------------

__global__ void __launch_bounds__(256, 6)
bias_kernel_2048(const int*   __restrict__ ts,
                 const float* __restrict__ pos,
                 const float* __restrict__ tsw,
                 float*       __restrict__ out,
                 int nb, ThrTab tab) {
    constexpr int N = 2048;
    __shared__ float4 s_tab[80];
    __shared__ float  s_pos[N + 16];

    const int b   = blockIdx.y;
    const int i0  = blockIdx.x * 8;           // grid.x = 256, exact
    const int tid = threadIdx.x;
    const int* trow = ts + b * N;

    if (tid < 80) {
        int k = tid;
        float wkm1 = tsw[min(max(k - 1, 0), nb)];
        float wk   = tsw[min(k, nb)];
        s_tab[k] = make_float4(tab.thr[k], wkm1, wk, 0.0f);
    }
    const int pbase = N - 8 - i0;             // >= 0
    #pragma unroll
    for (int u = 0; u < (N + 16 + 255) / 256; ++u) {
        int idx = tid + u * 256;
        if (idx < N + 16) {
            int g = pbase + idx;
            s_pos[idx] = (g <= 2 * N - 2) ? pos[g] : 0.0f;
        }
    }
    __syncthreads();

    float tnr[8];
    #pragma unroll
    for (int r = 0; r < 8; ++r) tnr[r] = (float)__ldg(&trow[min(i0 + r + 1, N - 1)]);

    float* oblk = out + ((size_t)b * N + i0) * (size_t)N;

    #pragma unroll 1
    for (int half = 0; half < 2; ++half) {
        const int jj = tid * 4 + half * 1024;
        int4 ti = *reinterpret_cast<const int4*>(trow + jj);
        const float tv0 = (float)ti.x, tv1 = (float)ti.y,
                    tv2 = (float)ti.z, tv3 = (float)ti.w;
        float4 p0 = *reinterpret_cast<const float4*>(s_pos + jj);
        float4 p1 = *reinterpret_cast<const float4*>(s_pos + jj + 4);
        float4 p2 = *reinterpret_cast<const float4*>(s_pos + jj + 8);
        const float pw[12] = {p0.x, p0.y, p0.z, p0.w,
                              p1.x, p1.y, p1.z, p1.w,
                              p2.x, p2.y, p2.z, p2.w};
        float* op = oblk + jj;

        #pragma unroll
        for (int r = 0; r < 8; ++r) {
            const float tn = tnr[r];
            float w0, w1, w2, w3;
            {
                float x = fmaxf(fabsf(tn - tv0), 1.0f);
                float q = fmaf(__log2f(x), 2.3028145f, 1.25e-4f);
                float4 te = s_tab[(int)q];
                w0 = (x < te.x) ? te.y : te.z;
            }
            {
                float x = fmaxf(fabsf(tn - tv1), 1.0f);
                float q = fmaf(__log2f(x), 2.3028145f, 1.25e-4f);
                float4 te = s_tab[(int)q];
                w1 = (x < te.x) ? te.y : te.z;
            }
            {
                float x = fmaxf(fabsf(tn - tv2), 1.0f);
                float q = fmaf(__log2f(x), 2.3028145f, 1.25e-4f);
                float4 te = s_tab[(int)q];
                w2 = (x < te.x) ? te.y : te.z;
            }
            {
                float x = fmaxf(fabsf(tn - tv3), 1.0f);
                float q = fmaf(__log2f(x), 2.3028145f, 1.25e-4f);
                float4 te = s_tab[(int)q];
                w3 = (x < te.x) ? te.y : te.z;
            }
            float4 o;
            o.x = w0 + pw[7 - r];
            o.y = w1 + pw[8 - r];
            o.z = w2 + pw[9 - r];
            o.w = w3 + pw[10 - r];
            *reinterpret_cast<float4*>(op + r * N) = o;   // immediate offset
        }
    }
}

// ---------------- generic fallback (R6) ----------------

__global__ void __launch_bounds__(256)
bias_kernel_gen(const int*   __restrict__ ts,
                const float* __restrict__ pos,
                const float* __restrict__ tsw,
                float*       __restrict__ out,
                int n, int nb, ThrTab tab) {
    extern __shared__ float sm[];
    float4* s_tab = (float4*)sm;
    float*  s_pos = sm + 320;

    const int b   = blockIdx.y;
    const int i0  = blockIdx.x * 8;
    const int tid = threadIdx.x;
    const int* trow = ts + (size_t)b * n;

    if (tid < 80) {
        int k = tid;
        float wkm1 = tsw[min(max(k - 1, 0), nb)];
        float wk   = tsw[min(k, nb)];
        s_tab[k] = make_float4(tab.thr[k], wkm1, wk, 0.0f);
    }
    const int pbase = n - 8 - i0;
    for (int idx = tid; idx < n + 16; idx += 256) {
        int g = pbase + idx;
        s_pos[idx] = (g >= 0 && g <= 2 * n - 2) ? pos[g] : 0.0f;
    }
    __syncthreads();

    float tnr[8];
    #pragma unroll
    for (int r = 0; r < 8; ++r) tnr[r] = (float)__ldg(&trow[min(i0 + r + 1, n - 1)]);

    const bool full = (i0 + 8 <= n);
    float* oblk = out + ((size_t)b * n + i0) * (size_t)n;

    for (int jj = tid * 4; jj < n; jj += 1024) {
        int4 ti = *reinterpret_cast<const int4*>(trow + jj);
        const float tv0 = (float)ti.x, tv1 = (float)ti.y,
                    tv2 = (float)ti.z, tv3 = (float)ti.w;
        float4 p0 = *reinterpret_cast<const float4*>(s_pos + jj);
        float4 p1 = *reinterpret_cast<const float4*>(s_pos + jj + 4);
        float4 p2 = *reinterpret_cast<const float4*>(s_pos + jj + 8);
        const float pw[12] = {p0.x, p0.y, p0.z, p0.w,
                              p1.x, p1.y, p1.z, p1.w,
                              p2.x, p2.y, p2.z, p2.w};
        float* op = oblk + jj;

        #pragma unroll
        for (int r = 0; r < 8; ++r) {
            const float tn = tnr[r];
            float w0, w1, w2, w3;
            {
                float x = fmaxf(fabsf(tn - tv0), 1.0f);
                float q = fmaf(__log2f(x), 2.3028145f, 1.25e-4f);
                float4 te = s_tab[(int)q];
                w0 = (x < te.x) ? te.y : te.z;
            }
            {
                float x = fmaxf(fabsf(tn - tv1), 1.0f);
                float q = fmaf(__log2f(x), 2.3028145f, 1.25e-4f);
                float4 te = s_tab[(int)q];
                w1 = (x < te.x) ? te.y : te.z;
            }
            {
                float x = fmaxf(fabsf(tn - tv2), 1.0f);
                float q = fmaf(__log2f(x), 2.3028145f, 1.25e-4f);
                float4 te = s_tab[(int)q];
                w2 = (x < te.x) ? te.y : te.z;
            }
            {
                float x = fmaxf(fabsf(tn - tv3), 1.0f);
                float q = fmaf(__log2f(x), 2.3028145f, 1.25e-4f);
                float4 te = s_tab[(int)q];
                w3 = (x < te.x) ? te.y : te.z;
            }
            if (full || i0 + r < n) {
                float4 o;
                o.x = w0 + pw[7 - r];
                o.y = w1 + pw[8 - r];
                o.z = w2 + pw[9 - r];
                o.w = w3 + pw[10 - r];
                *reinterpret_cast<float4*>(op) = o;
            }
            op += n;
        }
    }
}

static void build_thresholds_host(ThrTab* tab) {
    typedef union { float f; unsigned u; } FU;
    for (int k = 0; k < 80; ++k) {
        if (k == 0) { tab->thr[0] = 1.0f; continue; }
        volatile float kb = 0.301f;                  // force f32 division semantics
        FU l; l.f = (float)(0.301 * (double)k);
        while (!((float)(l.f / kb) >= (float)k)) l.u += 1u;
        for (;;) {
            FU p; p.u = l.u - 1u;
            if ((float)(p.f / kb) >= (float)k) l.u = p.u; else break;
        }
        FU x; x.f = (float)exp((double)l.f);
        while (!((float)log((double)x.f) >= l.f)) x.u += 1u;
        for (;;) {
            FU p; p.u = x.u - 1u;
            if ((float)log((double)p.f) >= l.f) x.u = p.u; else break;
        }
        tab->thr[k] = x.f;
    }
}

extern "C" void kernel_launch(void* const* d_in, const int* in_sizes, int n_in,
                              void* d_out, int out_size) {
    const int*   ts  = (const int*)d_in[0];     // timestamps (B*N) int32
    const float* pos = (const float*)d_in[1];   // pos_biases (2N-1) f32
    const float* tsw = (const float*)d_in[2];   // ts_w (nb+1) f32

    const int n  = (in_sizes[1] + 1) / 2;
    const int B  = in_sizes[0] / n;
    const int nb = in_sizes[2] - 1;

    ThrTab tab;
    build_thresholds_host(&tab);

    if (n == 2048 && nb < 80) {
        dim3 grid(256, B);
        bias_kernel_2048<<<grid, 256>>>(ts, pos, tsw, (float*)d_out, nb, tab);
    } else {
        size_t smem = (size_t)(320 + n + 16) * sizeof(float);
        dim3 grid((n + 7) / 8, B);
        bias_kernel_gen<<<grid, 256, smem>>>(ts, pos, tsw, (float*)d_out, n, nb, tab);
    }
}

// round 14
// speedup vs baseline: 1.3103x; 1.1609x over previous
#include <cuda_runtime.h>
#include <math.h>

// out[b,i,j] = pos_biases[j - i + n - 1]
//            + ts_w[ clamp( floor( log(clip(|f32(t[min(i+1,n-1)]) - f32(t[j])|, 1, 1e9)) / 0.301 ), 0, nb ) ]
//
// R6 exact core: biased-trunc __log2f + host-built ulp-exact threshold table
// fused as (thr[k], w[k-1], w[k]); one LDS.128 + compare/select per element.
// R13: FIXED dispatch (R12's `nb < 80` guard wrongly disabled the specialized
// kernel — nb=128 here; k <= 68 < 80 always since x <= 1e9, and the table
// already folds min(k, nb)). n==2048 path: immediate-offset stores, no tail
// predicates, launch_bounds(256,6). rel_err identical: 4.933e-4.

struct ThrTab { float thr[80]; };

// ---------------- specialized kernel: n == 2048 ----------------

__global__ void __launch_bounds__(256, 6)
bias_kernel_2048(const int*   __restrict__ ts,
                 const float* __restrict__ pos,
                 const float* __restrict__ tsw,
                 float*       __restrict__ out,
                 int nb, ThrTab tab) {
    constexpr int N = 2048;
    __shared__ float4 s_tab[80];
    __shared__ float  s_pos[N + 16];

    const int b   = blockIdx.y;
    const int i0  = blockIdx.x * 8;           // grid.x = 256, exact
    const int tid = threadIdx.x;
    const int* trow = ts + b * N;

    if (tid < 80) {
        int k = tid;
        float wkm1 = tsw[min(max(k - 1, 0), nb)];
        float wk   = tsw[min(k, nb)];
        s_tab[k] = make_float4(tab.thr[k], wkm1, wk, 0.0f);
    }
    const int pbase = N - 8 - i0;             // >= 0
    #pragma unroll
    for (int u = 0; u < (N + 16 + 255) / 256; ++u) {
        int idx = tid + u * 256;
        if (idx < N + 16) {
            int g = pbase + idx;
            s_pos[idx] = (g <= 2 * N - 2) ? pos[g] : 0.0f;
        }
    }
    __syncthreads();

    float tnr[8];
    #pragma unroll
    for (int r = 0; r < 8; ++r) tnr[r] = (float)__ldg(&trow[min(i0 + r + 1, N - 1)]);

    float* oblk = out + ((size_t)b * N + i0) * (size_t)N;

    #pragma unroll 1
    for (int half = 0; half < 2; ++half) {
        const int jj = tid * 4 + half * 1024;
        int4 ti = *reinterpret_cast<const int4*>(trow + jj);
        const float tv0 = (float)ti.x, tv1 = (float)ti.y,
                    tv2 = (float)ti.z, tv3 = (float)ti.w;
        float4 p0 = *reinterpret_cast<const float4*>(s_pos + jj);
        float4 p1 = *reinterpret_cast<const float4*>(s_pos + jj + 4);
        float4 p2 = *reinterpret_cast<const float4*>(s_pos + jj + 8);
        const float pw[12] = {p0.x, p0.y, p0.z, p0.w,
                              p1.x, p1.y, p1.z, p1.w,
                              p2.x, p2.y, p2.z, p2.w};
        float* op = oblk + jj;

        #pragma unroll
        for (int r = 0; r < 8; ++r) {
            const float tn = tnr[r];
            float w0, w1, w2, w3;
            {
                float x = fmaxf(fabsf(tn - tv0), 1.0f);
                float q = fmaf(__log2f(x), 2.3028145f, 1.25e-4f);
                float4 te = s_tab[(int)q];
                w0 = (x < te.x) ? te.y : te.z;
            }
            {
                float x = fmaxf(fabsf(tn - tv1), 1.0f);
                float q = fmaf(__log2f(x), 2.3028145f, 1.25e-4f);
                float4 te = s_tab[(int)q];
                w1 = (x < te.x) ? te.y : te.z;
            }
            {
                float x = fmaxf(fabsf(tn - tv2), 1.0f);
                float q = fmaf(__log2f(x), 2.3028145f, 1.25e-4f);
                float4 te = s_tab[(int)q];
                w2 = (x < te.x) ? te.y : te.z;
            }
            {
                float x = fmaxf(fabsf(tn - tv3), 1.0f);
                float q = fmaf(__log2f(x), 2.3028145f, 1.25e-4f);
                float4 te = s_tab[(int)q];
                w3 = (x < te.x) ? te.y : te.z;
            }
            float4 o;
            o.x = w0 + pw[7 - r];
            o.y = w1 + pw[8 - r];
            o.z = w2 + pw[9 - r];
            o.w = w3 + pw[10 - r];
            *reinterpret_cast<float4*>(op + r * N) = o;   // immediate offset
        }
    }
}

// ---------------- generic fallback (R6) ----------------

__global__ void __launch_bounds__(256)
bias_kernel_gen(const int*   __restrict__ ts,
                const float* __restrict__ pos,
                const float* __restrict__ tsw,
                float*       __restrict__ out,
                int n, int nb, ThrTab tab) {
    extern __shared__ float sm[];
    float4* s_tab = (float4*)sm;
    float*  s_pos = sm + 320;

    const int b   = blockIdx.y;
    const int i0  = blockIdx.x * 8;
    const int tid = threadIdx.x;
    const int* trow = ts + (size_t)b * n;

    if (tid < 80) {
        int k = tid;
        float wkm1 = tsw[min(max(k - 1, 0), nb)];
        float wk   = tsw[min(k, nb)];
        s_tab[k] = make_float4(tab.thr[k], wkm1, wk, 0.0f);
    }
    const int pbase = n - 8 - i0;
    for (int idx = tid; idx < n + 16; idx += 256) {
        int g = pbase + idx;
        s_pos[idx] = (g >= 0 && g <= 2 * n - 2) ? pos[g] : 0.0f;
    }
    __syncthreads();

    float tnr[8];
    #pragma unroll
    for (int r = 0; r < 8; ++r) tnr[r] = (float)__ldg(&trow[min(i0 + r + 1, n - 1)]);

    const bool full = (i0 + 8 <= n);
    float* oblk = out + ((size_t)b * n + i0) * (size_t)n;

    for (int jj = tid * 4; jj < n; jj += 1024) {
        int4 ti = *reinterpret_cast<const int4*>(trow + jj);
        const float tv0 = (float)ti.x, tv1 = (float)ti.y,
                    tv2 = (float)ti.z, tv3 = (float)ti.w;
        float4 p0 = *reinterpret_cast<const float4*>(s_pos + jj);
        float4 p1 = *reinterpret_cast<const float4*>(s_pos + jj + 4);
        float4 p2 = *reinterpret_cast<const float4*>(s_pos + jj + 8);
        const float pw[12] = {p0.x, p0.y, p0.z, p0.w,
                              p1.x, p1.y, p1.z, p1.w,
                              p2.x, p2.y, p2.z, p2.w};
        float* op = oblk + jj;

        #pragma unroll
        for (int r = 0; r < 8; ++r) {
            const float tn = tnr[r];
            float w0, w1, w2, w3;
            {
                float x = fmaxf(fabsf(tn - tv0), 1.0f);
                float q = fmaf(__log2f(x), 2.3028145f, 1.25e-4f);
                float4 te = s_tab[(int)q];
                w0 = (x < te.x) ? te.y : te.z;
            }
            {
                float x = fmaxf(fabsf(tn - tv1), 1.0f);
                float q = fmaf(__log2f(x), 2.3028145f, 1.25e-4f);
                float4 te = s_tab[(int)q];
                w1 = (x < te.x) ? te.y : te.z;
            }
            {
                float x = fmaxf(fabsf(tn - tv2), 1.0f);
                float q = fmaf(__log2f(x), 2.3028145f, 1.25e-4f);
                float4 te = s_tab[(int)q];
                w2 = (x < te.x) ? te.y : te.z;
            }
            {
                float x = fmaxf(fabsf(tn - tv3), 1.0f);
                float q = fmaf(__log2f(x), 2.3028145f, 1.25e-4f);
                float4 te = s_tab[(int)q];
                w3 = (x < te.x) ? te.y : te.z;
            }
            if (full || i0 + r < n) {
                float4 o;
                o.x = w0 + pw[7 - r];
                o.y = w1 + pw[8 - r];
                o.z = w2 + pw[9 - r];
                o.w = w3 + pw[10 - r];
                *reinterpret_cast<float4*>(op) = o;
            }
            op += n;
        }
    }
}

static void build_thresholds_host(ThrTab* tab) {
    typedef union { float f; unsigned u; } FU;
    for (int k = 0; k < 80; ++k) {
        if (k == 0) { tab->thr[0] = 1.0f; continue; }
        volatile float kb = 0.301f;                  // force f32 division semantics
        FU l; l.f = (float)(0.301 * (double)k);
        while (!((float)(l.f / kb) >= (float)k)) l.u += 1u;
        for (;;) {
            FU p; p.u = l.u - 1u;
            if ((float)(p.f / kb) >= (float)k) l.u = p.u; else break;
        }
        FU x; x.f = (float)exp((double)l.f);
        while (!((float)log((double)x.f) >= l.f)) x.u += 1u;
        for (;;) {
            FU p; p.u = x.u - 1u;
            if ((float)log((double)p.f) >= l.f) x.u = p.u; else break;
        }
        tab->thr[k] = x.f;
    }
}

extern "C" void kernel_launch(void* const* d_in, const int* in_sizes, int n_in,
                              void* d_out, int out_size) {
    const int*   ts  = (const int*)d_in[0];     // timestamps (B*N) int32
    const float* pos = (const float*)d_in[1];   // pos_biases (2N-1) f32
    const float* tsw = (const float*)d_in[2];   // ts_w (nb+1) f32

    const int n  = (in_sizes[1] + 1) / 2;
    const int B  = in_sizes[0] / n;
    const int nb = in_sizes[2] - 1;

    ThrTab tab;
    build_thresholds_host(&tab);

    if (n == 2048) {
        // bucket index k <= 68 always (x <= 1e9); table folds min(k, nb) for any nb
        dim3 grid(256, B);
        bias_kernel_2048<<<grid, 256>>>(ts, pos, tsw, (float*)d_out, nb, tab);
    } else {
        size_t smem = (size_t)(320 + n + 16) * sizeof(float);
        dim3 grid((n + 7) / 8, B);
        bias_kernel_gen<<<grid, 256, smem>>>(ts, pos, tsw, (float*)d_out, n, nb, tab);
    }
}